// round 6
// baseline (speedup 1.0000x reference)
#include <cuda_runtime.h>

// QuantumEvolution: B=512 x M=2048. SU(2) step propagators = unit quaternions;
// prefix product via warp shuffle scan. TPB=256, 8 steps/thread, L[8] in regs,
// fully independent epilogue, one full-block output staging pass (53KB dyn smem).

#define TPB    256
#define STEPS  8
#define MSTEPS 2048
#define BREAL  512

// Dynamic smem layout (float4 units), regions time-disjoint:
//   input phase: pulses rows [0, 256*5) f4  |  noise rows [256*5, 256*5+256*3) f4
//   stage phase: rows of 13 f4 (48 floats + 4 pad), 256*13 f4 = 53248 B
#define SM_P_F4   0
#define SM_N_F4   (256 * 5)
#define SM_F4     (256 * 13)
#define SMEM_BYTES (SM_F4 * 16)

__device__ __forceinline__ float4 qmul(float4 a, float4 b) {
    // Hamilton product a*b; quaternion (w,x,y,z) in (x,y,z,w) fields.
    float4 r;
    r.x = a.x * b.x - a.y * b.y - a.z * b.z - a.w * b.w;
    r.y = a.x * b.y + a.y * b.x + a.z * b.w - a.w * b.z;
    r.z = a.x * b.z - a.y * b.w + a.z * b.x + a.w * b.y;
    r.w = a.x * b.w + a.y * b.z - a.z * b.y + a.w * b.x;
    return r;
}

__device__ __forceinline__ float4 shfl_up_q(float4 v, int off) {
    float4 r;
    r.x = __shfl_up_sync(0xFFFFFFFFu, v.x, off);
    r.y = __shfl_up_sync(0xFFFFFFFFu, v.y, off);
    r.z = __shfl_up_sync(0xFFFFFFFFu, v.z, off);
    r.w = __shfl_up_sync(0xFFFFFFFFu, v.w, off);
    return r;
}

__device__ __forceinline__ float4 stepq(float hx, float hy, float hz) {
    const float dt = 1.0f / 2048.0f;
    float t2 = (dt * dt) * (hx * hx + hy * hy + hz * hz);   // theta^2 <= ~1.5e-5
    float c = 1.f - t2 * (0.5f - t2 * (1.f / 24.f));        // cos(theta)
    float k = dt * (1.f - t2 * ((1.f / 6.f) - t2 * (1.f / 120.f)));  // dt*sinc
    return make_float4(c, k * hx, k * hy, k * hz);
}

__global__ __launch_bounds__(TPB, 4)
void qe_kernel(const float* __restrict__ noise,
               const float* __restrict__ pulses,
               float* __restrict__ out) {
    extern __shared__ float4 sm4[];
    __shared__ float4 wtot[TPB / 32];

    const int b    = blockIdx.x;
    const int tid  = threadIdx.x;
    const int lane = tid & 31;
    const int wid  = tid >> 5;

    // ---- Coalesced input staging: gmem f4 -> padded smem rows ----
    // pulses: 1024 f4/block; row t gets 4 f4 at stride 5 (conflict-free LDS.128).
    const float4* gp = reinterpret_cast<const float4*>(pulses + (size_t)b * MSTEPS * 2);
#pragma unroll
    for (int k = 0; k < 4; k++) {
        int g = tid + TPB * k;
        sm4[SM_P_F4 + (g >> 2) * 5 + (g & 3)] = gp[g];
    }
    // noise: 512 f4/block; row t gets 2 f4 at stride 3.
    const float4* gn = reinterpret_cast<const float4*>(noise + (size_t)b * MSTEPS);
#pragma unroll
    for (int k = 0; k < 2; k++) {
        int g = tid + TPB * k;
        sm4[SM_N_F4 + (g >> 1) * 3 + (g & 1)] = gn[g];
    }
    __syncthreads();

    // ---- Read own inputs (conflict-free f4 LDS), build local prefixes L[8] ----
    const float4 pa = sm4[SM_P_F4 + tid * 5 + 0];
    const float4 pb = sm4[SM_P_F4 + tid * 5 + 1];
    const float4 pc = sm4[SM_P_F4 + tid * 5 + 2];
    const float4 pd = sm4[SM_P_F4 + tid * 5 + 3];
    const float4 na = sm4[SM_N_F4 + tid * 3 + 0];
    const float4 nb = sm4[SM_N_F4 + tid * 3 + 1];

    float4 L[STEPS];
    L[0] = stepq(pa.x, pa.y, 0.5f + na.x);
    L[1] = qmul(stepq(pa.z, pa.w, 0.5f + na.y), L[0]);
    L[2] = qmul(stepq(pb.x, pb.y, 0.5f + na.z), L[1]);
    L[3] = qmul(stepq(pb.z, pb.w, 0.5f + na.w), L[2]);
    L[4] = qmul(stepq(pc.x, pc.y, 0.5f + nb.x), L[3]);
    L[5] = qmul(stepq(pc.z, pc.w, 0.5f + nb.y), L[4]);
    L[6] = qmul(stepq(pd.x, pd.y, 0.5f + nb.z), L[5]);
    L[7] = qmul(stepq(pd.z, pd.w, 0.5f + nb.w), L[6]);

    // ---- Warp-level inclusive scan of chunk products ----
    float4 v = L[7];
#pragma unroll
    for (int off = 1; off < 32; off <<= 1) {
        float4 o = shfl_up_q(v, off);
        if (lane >= off) v = qmul(v, o);
    }
    if (lane == 31) wtot[wid] = v;
    __syncthreads();

    // Warp-exclusive prefix (uniform per warp, broadcast smem reads).
    float4 WE = make_float4(1.f, 0.f, 0.f, 0.f);
    for (int w = 0; w < wid; w++) WE = qmul(wtot[w], WE);

    float4 TE = shfl_up_q(v, 1);
    if (lane == 0) TE = make_float4(1.f, 0.f, 0.f, 0.f);
    const float4 E = qmul(TE, WE);   // exclusive global prefix for this chunk

    // ---- Epilogue: 8 independent composes; stage rows of 13 f4 (pad 1) ----
    float4* srow = &sm4[tid * 13];
#pragma unroll
    for (int j = 0; j < 4; j++) {                 // 2 steps -> 3 f4 stores
        float4 P0 = qmul(L[2 * j],     E);
        float4 P1 = qmul(L[2 * j + 1], E);
        float w0 = P0.x, x0 = P0.y, y0 = P0.z, z0 = P0.w;
        float w1 = P1.x, x1 = P1.y, y1 = P1.z, z1 = P1.w;
        srow[j * 3 + 0] = make_float4(2.f * (x0 * z0 + w0 * y0),
                                      2.f * (y0 * z0 - w0 * x0),
                                      1.f - 2.f * (x0 * x0 + y0 * y0),
                                      1.f - 2.f * (y0 * y0 + z0 * z0));
        srow[j * 3 + 1] = make_float4(2.f * (x0 * y0 + w0 * z0),
                                      2.f * (x0 * z0 - w0 * y0),
                                      2.f * (x1 * z1 + w1 * y1),
                                      2.f * (y1 * z1 - w1 * x1));
        srow[j * 3 + 2] = make_float4(1.f - 2.f * (x1 * x1 + y1 * y1),
                                      1.f - 2.f * (y1 * y1 + z1 * z1),
                                      2.f * (x1 * y1 + w1 * z1),
                                      2.f * (x1 * z1 - w1 * y1));
    }
    __syncthreads();

    // ---- Coalesced copy-out: 3072 f4/block = 12 f4/thread, contiguous ----
    float4* og = reinterpret_cast<float4*>(out + (size_t)b * (MSTEPS * 6));
#pragma unroll
    for (int k = 0; k < 12; k++) {
        int g4 = tid + TPB * k;
        int r  = g4 / 12;
        int c  = g4 - r * 12;
        og[g4] = sm4[r * 13 + c];
    }
}

extern "C" void kernel_launch(void* const* d_in, const int* in_sizes, int n_in,
                              void* d_out, int out_size) {
    const float* noise  = (const float*)d_in[0];   // [512, 2048, 1]
    const float* pulses = (const float*)d_in[1];   // [512, 2048, 2]
    if (in_sizes[0] > in_sizes[1]) {               // defensive: order by size
        const float* t = noise; noise = pulses; pulses = t;
    }
    static bool attr_set = false;
    if (!attr_set) {
        cudaFuncSetAttribute(qe_kernel,
                             cudaFuncAttributeMaxDynamicSharedMemorySize,
                             SMEM_BYTES);
        attr_set = true;
    }
    qe_kernel<<<BREAL, TPB, SMEM_BYTES>>>(noise, pulses, (float*)d_out);
}

// round 7
// speedup vs baseline: 1.1597x; 1.1597x over previous
#include <cuda_runtime.h>

// QuantumEvolution: B=512 x M=2048. SU(2) step propagators = unit quaternions;
// per-trajectory prefix product via warp shuffle scan. MIO-diet revision:
// direct vectorized global loads (no input staging, 2 barriers total),
// L[8] in regs, independent epilogue, smem transpose only for the output.

#define TPB    256
#define STEPS  8
#define MSTEPS 2048
#define BREAL  512

// Dynamic smem: output stage rows of 13 f4 (48 floats + 16B pad), 256 rows.
#define SM_F4      (256 * 13)
#define SMEM_BYTES (SM_F4 * 16)

__device__ __forceinline__ float4 qmul(float4 a, float4 b) {
    // Hamilton product a*b; quaternion (w,x,y,z) in (x,y,z,w) fields.
    float4 r;
    r.x = a.x * b.x - a.y * b.y - a.z * b.z - a.w * b.w;
    r.y = a.x * b.y + a.y * b.x + a.z * b.w - a.w * b.z;
    r.z = a.x * b.z - a.y * b.w + a.z * b.x + a.w * b.y;
    r.w = a.x * b.w + a.y * b.z - a.z * b.y + a.w * b.x;
    return r;
}

__device__ __forceinline__ float4 shfl_up_q(float4 v, int off) {
    float4 r;
    r.x = __shfl_up_sync(0xFFFFFFFFu, v.x, off);
    r.y = __shfl_up_sync(0xFFFFFFFFu, v.y, off);
    r.z = __shfl_up_sync(0xFFFFFFFFu, v.z, off);
    r.w = __shfl_up_sync(0xFFFFFFFFu, v.w, off);
    return r;
}

__device__ __forceinline__ float4 stepq(float hx, float hy, float hz) {
    const float dt = 1.0f / 2048.0f;
    float t2 = (dt * dt) * (hx * hx + hy * hy + hz * hz);   // theta^2 <= ~1.5e-5
    float c = 1.f - t2 * (0.5f - t2 * (1.f / 24.f));        // cos(theta)
    float k = dt * (1.f - t2 * ((1.f / 6.f) - t2 * (1.f / 120.f)));  // dt*sinc
    return make_float4(c, k * hx, k * hy, k * hz);
}

__global__ __launch_bounds__(TPB, 4)
void qe_kernel(const float* __restrict__ noise,
               const float* __restrict__ pulses,
               float* __restrict__ out) {
    extern __shared__ float4 sm4[];
    __shared__ float4 wtot[TPB / 32];

    const int b    = blockIdx.x;
    const int tid  = threadIdx.x;
    const int lane = tid & 31;
    const int wid  = tid >> 5;

    // ---- Direct vectorized loads: thread t owns steps 8t..8t+7 ----
    // pulses floats [16t,16t+16) = f4 [4t,4t+4); noise floats [8t,8t+8) = f4 [2t,2t+2).
    const float4* gp = reinterpret_cast<const float4*>(pulses + (size_t)b * MSTEPS * 2) + 4 * tid;
    const float4* gn = reinterpret_cast<const float4*>(noise  + (size_t)b * MSTEPS)     + 2 * tid;
    const float4 pa = gp[0], pb = gp[1], pc = gp[2], pd = gp[3];
    const float4 na = gn[0], nb = gn[1];

    // ---- Local inclusive prefixes L[8] (newer step on the left) ----
    float4 L[STEPS];
    L[0] = stepq(pa.x, pa.y, 0.5f + na.x);
    L[1] = qmul(stepq(pa.z, pa.w, 0.5f + na.y), L[0]);
    L[2] = qmul(stepq(pb.x, pb.y, 0.5f + na.z), L[1]);
    L[3] = qmul(stepq(pb.z, pb.w, 0.5f + na.w), L[2]);
    L[4] = qmul(stepq(pc.x, pc.y, 0.5f + nb.x), L[3]);
    L[5] = qmul(stepq(pc.z, pc.w, 0.5f + nb.y), L[4]);
    L[6] = qmul(stepq(pd.x, pd.y, 0.5f + nb.z), L[5]);
    L[7] = qmul(stepq(pd.z, pd.w, 0.5f + nb.w), L[6]);

    // ---- Warp-level inclusive scan of chunk products ----
    float4 v = L[7];
#pragma unroll
    for (int off = 1; off < 32; off <<= 1) {
        float4 o = shfl_up_q(v, off);
        if (lane >= off) v = qmul(v, o);
    }
    if (lane == 31) wtot[wid] = v;
    __syncthreads();

    // Warp-exclusive prefix (uniform per warp, broadcast smem reads).
    float4 WE = make_float4(1.f, 0.f, 0.f, 0.f);
#pragma unroll
    for (int w = 0; w < (TPB / 32) - 1; w++)
        if (w < wid) WE = qmul(wtot[w], WE);

    float4 TE = shfl_up_q(v, 1);
    if (lane == 0) TE = make_float4(1.f, 0.f, 0.f, 0.f);
    const float4 E = qmul(TE, WE);   // exclusive global prefix for this chunk

    // ---- Epilogue: 8 independent composes -> stage rows (13 f4, pad 1) ----
    float4* srow = &sm4[tid * 13];
#pragma unroll
    for (int j = 0; j < 4; j++) {                 // 2 steps -> 3 f4 stores
        float4 P0 = qmul(L[2 * j],     E);
        float4 P1 = qmul(L[2 * j + 1], E);
        float w0 = P0.x, x0 = P0.y, y0 = P0.z, z0 = P0.w;
        float w1 = P1.x, x1 = P1.y, y1 = P1.z, z1 = P1.w;
        srow[j * 3 + 0] = make_float4(2.f * (x0 * z0 + w0 * y0),
                                      2.f * (y0 * z0 - w0 * x0),
                                      1.f - 2.f * (x0 * x0 + y0 * y0),
                                      1.f - 2.f * (y0 * y0 + z0 * z0));
        srow[j * 3 + 1] = make_float4(2.f * (x0 * y0 + w0 * z0),
                                      2.f * (x0 * z0 - w0 * y0),
                                      2.f * (x1 * z1 + w1 * y1),
                                      2.f * (y1 * z1 - w1 * x1));
        srow[j * 3 + 2] = make_float4(1.f - 2.f * (x1 * x1 + y1 * y1),
                                      1.f - 2.f * (y1 * y1 + z1 * z1),
                                      2.f * (x1 * y1 + w1 * z1),
                                      2.f * (x1 * z1 - w1 * y1));
    }
    __syncthreads();

    // ---- Coalesced copy-out: 3072 f4/block = 12 f4/thread ----
    float4* og = reinterpret_cast<float4*>(out + (size_t)b * (MSTEPS * 6));
#pragma unroll
    for (int k = 0; k < 12; k++) {
        int g4 = tid + TPB * k;
        int r  = g4 / 12;
        int c  = g4 - r * 12;
        og[g4] = sm4[r * 13 + c];
    }
}

extern "C" void kernel_launch(void* const* d_in, const int* in_sizes, int n_in,
                              void* d_out, int out_size) {
    const float* noise  = (const float*)d_in[0];   // [512, 2048, 1]
    const float* pulses = (const float*)d_in[1];   // [512, 2048, 2]
    if (in_sizes[0] > in_sizes[1]) {               // defensive: order by size
        const float* t = noise; noise = pulses; pulses = t;
    }
    static bool attr_set = false;
    if (!attr_set) {
        cudaFuncSetAttribute(qe_kernel,
                             cudaFuncAttributeMaxDynamicSharedMemorySize,
                             SMEM_BYTES);
        attr_set = true;
    }
    qe_kernel<<<BREAL, TPB, SMEM_BYTES>>>(noise, pulses, (float*)d_out);
}

// round 8
// speedup vs baseline: 1.1830x; 1.0201x over previous
#include <cuda_runtime.h>
#include <cstdint>

// QuantumEvolution: B=512 x M=2048. SU(2) step propagators = unit quaternions;
// prefix product via warp shuffle scan. This revision cuts dynamic instructions:
// (1) warp-0 scan of warp totals replaces the per-thread redundant WE loop,
// (2) epilogue composes+expectations computed pairwise in packed f32x2 (FFMA2).

#define TPB    256
#define STEPS  8
#define MSTEPS 2048
#define BREAL  512

#define SM_F4      (256 * 13)        // output stage rows: 13 f4 (48 fl + pad)
#define SMEM_BYTES (SM_F4 * 16)

typedef unsigned long long u64;

// ---- packed f32x2 helpers (sm_103a FFMA2 path) ----
__device__ __forceinline__ u64 f2pack(float lo, float hi) {
    u64 d;
    asm("mov.b64 %0, {%1, %2};" : "=l"(d)
        : "r"(__float_as_uint(lo)), "r"(__float_as_uint(hi)));
    return d;
}
__device__ __forceinline__ void f2unpack(float& lo, float& hi, u64 s) {
    unsigned a, b;
    asm("mov.b64 {%0, %1}, %2;" : "=r"(a), "=r"(b) : "l"(s));
    lo = __uint_as_float(a); hi = __uint_as_float(b);
}
__device__ __forceinline__ u64 f2mul(u64 a, u64 b) {
    u64 d; asm("mul.rn.f32x2 %0, %1, %2;" : "=l"(d) : "l"(a), "l"(b)); return d;
}
__device__ __forceinline__ u64 f2fma(u64 a, u64 b, u64 c) {
    u64 d; asm("fma.rn.f32x2 %0, %1, %2, %3;" : "=l"(d) : "l"(a), "l"(b), "l"(c)); return d;
}
__device__ __forceinline__ u64 f2add(u64 a, u64 b) {
    u64 d; asm("add.rn.f32x2 %0, %1, %2;" : "=l"(d) : "l"(a), "l"(b)); return d;
}
__device__ __forceinline__ u64 f2neg(u64 a) {      // flip both sign bits
    u64 d; asm("xor.b64 %0, %1, 0x8000000080000000;" : "=l"(d) : "l"(a)); return d;
}

__device__ __forceinline__ float4 qmul(float4 a, float4 b) {
    // Hamilton product a*b; quaternion (w,x,y,z) in (x,y,z,w) fields.
    float4 r;
    r.x = a.x * b.x - a.y * b.y - a.z * b.z - a.w * b.w;
    r.y = a.x * b.y + a.y * b.x + a.z * b.w - a.w * b.z;
    r.z = a.x * b.z - a.y * b.w + a.z * b.x + a.w * b.y;
    r.w = a.x * b.w + a.y * b.z - a.z * b.y + a.w * b.x;
    return r;
}

__device__ __forceinline__ float4 shfl_up_q(float4 v, int off) {
    float4 r;
    r.x = __shfl_up_sync(0xFFFFFFFFu, v.x, off);
    r.y = __shfl_up_sync(0xFFFFFFFFu, v.y, off);
    r.z = __shfl_up_sync(0xFFFFFFFFu, v.z, off);
    r.w = __shfl_up_sync(0xFFFFFFFFu, v.w, off);
    return r;
}

__device__ __forceinline__ float4 stepq(float hx, float hy, float hz) {
    const float dt = 1.0f / 2048.0f;
    float t2 = (dt * dt) * (hx * hx + hy * hy + hz * hz);   // theta^2 <= ~1.5e-5
    float c = 1.f - t2 * (0.5f - t2 * (1.f / 24.f));        // cos(theta)
    float k = dt * (1.f - t2 * ((1.f / 6.f) - t2 * (1.f / 120.f)));  // dt*sinc
    return make_float4(c, k * hx, k * hy, k * hz);
}

__global__ __launch_bounds__(TPB, 4)
void qe_kernel(const float* __restrict__ noise,
               const float* __restrict__ pulses,
               float* __restrict__ out) {
    extern __shared__ float4 sm4[];
    __shared__ float4 wtot[TPB / 32];
    __shared__ float4 wscan[TPB / 32];

    const int b    = blockIdx.x;
    const int tid  = threadIdx.x;
    const int lane = tid & 31;
    const int wid  = tid >> 5;

    // ---- Direct vectorized loads: thread t owns steps 8t..8t+7 ----
    const float4* gp = reinterpret_cast<const float4*>(pulses + (size_t)b * MSTEPS * 2) + 4 * tid;
    const float4* gn = reinterpret_cast<const float4*>(noise  + (size_t)b * MSTEPS)     + 2 * tid;
    const float4 pa = gp[0], pb = gp[1], pc = gp[2], pd = gp[3];
    const float4 na = gn[0], nb = gn[1];

    // ---- Local inclusive prefixes L[8] (newer step on the left) ----
    float4 L[STEPS];
    L[0] = stepq(pa.x, pa.y, 0.5f + na.x);
    L[1] = qmul(stepq(pa.z, pa.w, 0.5f + na.y), L[0]);
    L[2] = qmul(stepq(pb.x, pb.y, 0.5f + na.z), L[1]);
    L[3] = qmul(stepq(pb.z, pb.w, 0.5f + na.w), L[2]);
    L[4] = qmul(stepq(pc.x, pc.y, 0.5f + nb.x), L[3]);
    L[5] = qmul(stepq(pc.z, pc.w, 0.5f + nb.y), L[4]);
    L[6] = qmul(stepq(pd.x, pd.y, 0.5f + nb.z), L[5]);
    L[7] = qmul(stepq(pd.z, pd.w, 0.5f + nb.w), L[6]);

    // ---- Warp-level inclusive scan of chunk products ----
    float4 v = L[7];
#pragma unroll
    for (int off = 1; off < 32; off <<= 1) {
        float4 o = shfl_up_q(v, off);
        if (lane >= off) v = qmul(v, o);
    }
    if (lane == 31) wtot[wid] = v;
    __syncthreads();

    // ---- Warp 0 scans the 8 warp totals (3 shuffle rounds) ----
    if (wid == 0) {
        float4 t = wtot[lane & 7];
#pragma unroll
        for (int off = 1; off < 8; off <<= 1) {
            float4 o = shfl_up_q(t, off);
            if (lane >= off && lane < 8) t = qmul(t, o);
        }
        if (lane < 8) wscan[lane] = t;
    }
    __syncthreads();

    float4 WE = (wid > 0) ? wscan[wid - 1] : make_float4(1.f, 0.f, 0.f, 0.f);
    float4 TE = shfl_up_q(v, 1);
    if (lane == 0) TE = make_float4(1.f, 0.f, 0.f, 0.f);
    const float4 E = qmul(TE, WE);   // exclusive global prefix for this chunk

    // ---- Packed-f32x2 epilogue: pairs (2j, 2j+1) are independent ----
    // E component packs (broadcast) + negated variants, hoisted once.
    const u64 Ew  = f2pack(E.x, E.x), Ex  = f2pack(E.y, E.y);
    const u64 Ey  = f2pack(E.z, E.z), Ez  = f2pack(E.w, E.w);
    const u64 nEx = f2neg(Ex), nEy = f2neg(Ey), nEz = f2neg(Ez);
    const u64 M2  = f2pack(-2.f, -2.f), ONE = f2pack(1.f, 1.f);

    float4* srow = &sm4[tid * 13];
#pragma unroll
    for (int j = 0; j < 4; j++) {
        const float4 A = L[2 * j], Bq = L[2 * j + 1];
        // a = packed pair of chunk-local prefixes (quaternion (w,x,y,z)).
        const u64 aw = f2pack(A.x, Bq.x), ax = f2pack(A.y, Bq.y);
        const u64 ay = f2pack(A.z, Bq.z), az = f2pack(A.w, Bq.w);
        // P = a * E (Hamilton), packed: 16 FFMA2.
        u64 Pw = f2fma(az, nEz, f2fma(ay, nEy, f2fma(ax, nEx, f2mul(aw, Ew))));
        u64 Px = f2fma(az, nEy, f2fma(ay,  Ez, f2fma(ax,  Ew, f2mul(aw, Ex))));
        u64 Py = f2fma(az,  Ex, f2fma(ay,  Ew, f2fma(ax, nEz, f2mul(aw, Ey))));
        u64 Pz = f2fma(az,  Ew, f2fma(ay, nEx, f2fma(ax,  Ey, f2mul(aw, Ez))));
        // Expectations (rotation-matrix columns), packed.
        u64 nPw = f2neg(Pw);
        u64 xz  = f2mul(Px, Pz);
        u64 s0  = f2fma(Pw, Py, xz);  s0 = f2add(s0, s0);          // 2(xz+wy)
        u64 s1  = f2fma(nPw, Px, f2mul(Py, Pz)); s1 = f2add(s1, s1); // 2(yz-wx)
        u64 s2  = f2fma(f2fma(Py, Py, f2mul(Px, Px)), M2, ONE);    // 1-2(xx+yy)
        u64 s3  = f2fma(f2fma(Pz, Pz, f2mul(Py, Py)), M2, ONE);    // 1-2(yy+zz)
        u64 s4  = f2fma(Pw, Pz, f2mul(Px, Py)); s4 = f2add(s4, s4); // 2(xy+wz)
        u64 s5  = f2fma(nPw, Py, xz); s5 = f2add(s5, s5);          // 2(xz-wy)
        // Unpack and store in output layout [step][6].
        float a0, b0, a1, b1, a2, b2, a3, b3, a4, b4, a5, b5;
        f2unpack(a0, b0, s0); f2unpack(a1, b1, s1); f2unpack(a2, b2, s2);
        f2unpack(a3, b3, s3); f2unpack(a4, b4, s4); f2unpack(a5, b5, s5);
        srow[j * 3 + 0] = make_float4(a0, a1, a2, a3);
        srow[j * 3 + 1] = make_float4(a4, a5, b0, b1);
        srow[j * 3 + 2] = make_float4(b2, b3, b4, b5);
    }
    __syncthreads();

    // ---- Coalesced copy-out: 3072 f4/block = 12 f4/thread ----
    float4* og = reinterpret_cast<float4*>(out + (size_t)b * (MSTEPS * 6));
#pragma unroll
    for (int k = 0; k < 12; k++) {
        int g4 = tid + TPB * k;
        int r  = g4 / 12;
        int c  = g4 - r * 12;
        og[g4] = sm4[r * 13 + c];
    }
}

extern "C" void kernel_launch(void* const* d_in, const int* in_sizes, int n_in,
                              void* d_out, int out_size) {
    const float* noise  = (const float*)d_in[0];   // [512, 2048, 1]
    const float* pulses = (const float*)d_in[1];   // [512, 2048, 2]
    if (in_sizes[0] > in_sizes[1]) {               // defensive: order by size
        const float* t = noise; noise = pulses; pulses = t;
    }
    static bool attr_set = false;
    if (!attr_set) {
        cudaFuncSetAttribute(qe_kernel,
                             cudaFuncAttributeMaxDynamicSharedMemorySize,
                             SMEM_BYTES);
        attr_set = true;
    }
    qe_kernel<<<BREAL, TPB, SMEM_BYTES>>>(noise, pulses, (float*)d_out);
}